// round 6
// baseline (speedup 1.0000x reference)
#include <cuda_runtime.h>
#include <math.h>

// Problem constants (fixed by the reference)
#define NODES   100000
#define EDGES   1600000
#define HID     128
#define T_STEPS 24
#define DYN     8
#define STAT    16
#define KLSTM   136            // DYN + HID
#define G4      512            // 4*HID gates

// ---------------- scratch (static device globals; no allocation) -------------
__device__ float4 g_h4  [NODES * HID / 4];        // 51.2 MB  LSTM hidden
__device__ float4 g_c4  [NODES * HID / 4];        // 51.2 MB  LSTM cell
__device__ float4 g_z4  [(size_t)NODES * G4 / 4]; // 204.8 MB gate preacts
__device__ float4 g_xw4 [NODES * HID / 4];        // 51.2 MB  X @ W
__device__ float4 g_agg4[NODES * HID / 4];        // 51.2 MB  aggregated
__device__ float4 g_x4  [NODES * HID / 4];        // 51.2 MB  layer activations
__device__ float  g_wcatT[KLSTM * G4];            // [K][512] transposed combined W
__device__ float  g_bcat [G4];
__device__ float  g_dis  [NODES];                 // deg, then deg^-1/2
__device__ float  g_norm [EDGES];
__device__ int    g_any;                          // edge dtype detector: 0 => int64

#define F(p) ((float*)(p))

__device__ __forceinline__ float sg(float x) { return 1.f / (1.f + __expf(-x)); }

// Logical element p of edge_index (shape [2,E] flattened), robust to the
// buffer being int32 OR little-endian int64 (indices < 2^31 => odd words 0).
__device__ __forceinline__ unsigned load_edge(const int* __restrict__ ei, size_t p) {
    return (g_any == 0) ? (unsigned)ei[2 * p]   // int64: low word
                        : (unsigned)ei[p];      // int32
}

// ---------------- setup kernels ---------------------------------------------
__global__ void k_build_wcat(const float* __restrict__ Wih, const float* __restrict__ Whh,
                             const float* __restrict__ bih, const float* __restrict__ bhh) {
    int i = blockIdx.x * blockDim.x + threadIdx.x;
    if (i == 0) g_any = 0;                       // reset detector every call
    if (i < KLSTM * G4) {
        int k = i / G4, g = i % G4;
        g_wcatT[i] = (k < DYN) ? Wih[g * DYN + k] : Whh[g * HID + (k - DYN)];
    }
    if (i < G4) g_bcat[i] = bih[i] + bhh[i];
}

// OR the first 1024 odd 32-bit words: nonzero => int32 layout.
__global__ void k_det_scan(const int* __restrict__ ei) {
    int i = blockIdx.x * blockDim.x + threadIdx.x;   // 1024 threads
    int v = ei[2 * i + 1];
    if (v) atomicOr(&g_any, 1);
}

__global__ void k_zero_hc(int n) {
    int i = blockIdx.x * blockDim.x + threadIdx.x;
    if (i < n) { F(g_h4)[i] = 0.f; F(g_c4)[i] = 0.f; }
}

// ---------------- LSTM step GEMM: Z = [x_t | h] @ WcatT + bcat ---------------
// 128x128 block tile, BK=8, 256 threads, 8x8 microtile.
__global__ __launch_bounds__(256) void k_lstm_gemm(const float* __restrict__ xd, int t, int N) {
    __shared__ float As[8][132];   // pad 132: (4k+m)%32 hits all banks on store
    __shared__ float Bs[8][128];
    const float* __restrict__ h = F(g_h4);
    int bm = blockIdx.x * 128;
    int bn = blockIdx.y * 128;
    int tid = threadIdx.x;
    int tm = (tid >> 4) << 3;
    int tn = (tid & 15) << 3;
    float acc[8][8] = {};

    for (int k0 = 0; k0 < KLSTM; k0 += 8) {
        #pragma unroll
        for (int i = 0; i < 4; i++) {
            int idx = tid + (i << 8);
            int k = idx & 7, m = idx >> 3;            // k-fast: coalesced A rows
            int gm = bm + m, gk = k0 + k;
            float v = 0.f;
            if (gm < N)
                v = (gk < DYN) ? xd[(size_t)gm * (T_STEPS * DYN) + t * DYN + gk]
                               : h[(size_t)gm * HID + (gk - DYN)];
            As[k][m] = v;
            int n = idx & 127, k2 = idx >> 7;         // n-fast: coalesced B rows
            Bs[k2][n] = g_wcatT[(size_t)(k0 + k2) * G4 + bn + n];
        }
        __syncthreads();
        #pragma unroll
        for (int k = 0; k < 8; k++) {
            float a[8], b[8];
            #pragma unroll
            for (int i = 0; i < 8; i++) a[i] = As[k][tm + i];
            #pragma unroll
            for (int j = 0; j < 8; j++) b[j] = Bs[k][tn + j];
            #pragma unroll
            for (int i = 0; i < 8; i++)
                #pragma unroll
                for (int j = 0; j < 8; j++) acc[i][j] = fmaf(a[i], b[j], acc[i][j]);
        }
        __syncthreads();
    }
    float* Z = F(g_z4);
    #pragma unroll
    for (int i = 0; i < 8; i++) {
        int gm = bm + tm + i;
        if (gm >= N) continue;
        #pragma unroll
        for (int j = 0; j < 8; j += 4) {
            int g = bn + tn + j;
            float4 v = make_float4(acc[i][j]   + g_bcat[g],
                                   acc[i][j+1] + g_bcat[g+1],
                                   acc[i][j+2] + g_bcat[g+2],
                                   acc[i][j+3] + g_bcat[g+3]);
            *(float4*)(Z + (size_t)gm * G4 + g) = v;
        }
    }
}

// ---------------- gate pointwise + state update ------------------------------
__global__ void k_gates(int N) {
    int i = blockIdx.x * blockDim.x + threadIdx.x;   // over N*32 (float4 grains)
    if (i >= N * (HID / 4)) return;
    int n = i >> 5, q = i & 31;
    const float4* z = (const float4*)(F(g_z4) + (size_t)n * G4);
    float4 zi = z[q], zf = z[32 + q], zg = z[64 + q], zo = z[96 + q];
    float4 c = g_c4[i];
    float4 nc, nh;
    nc.x = sg(zf.x) * c.x + sg(zi.x) * tanhf(zg.x);
    nc.y = sg(zf.y) * c.y + sg(zi.y) * tanhf(zg.y);
    nc.z = sg(zf.z) * c.z + sg(zi.z) * tanhf(zg.z);
    nc.w = sg(zf.w) * c.w + sg(zi.w) * tanhf(zg.w);
    nh.x = sg(zo.x) * tanhf(nc.x);
    nh.y = sg(zo.y) * tanhf(nc.y);
    nh.z = sg(zo.z) * tanhf(nc.z);
    nh.w = sg(zo.w) * tanhf(nc.w);
    g_c4[i] = nc;
    g_h4[i] = nh;
}

// ---------------- GCN normalization -----------------------------------------
__global__ void k_deg_init(int N) {
    int i = blockIdx.x * blockDim.x + threadIdx.x;
    if (i < N) g_dis[i] = 1.0f;                       // self-loop weight
}
__global__ void k_deg_scatter(const int* __restrict__ ei,
                              const float* __restrict__ ew, int E, int N) {
    int e = blockIdx.x * blockDim.x + threadIdx.x;
    if (e >= E) return;
    unsigned c = load_edge(ei, (size_t)E + e);
    if (c < (unsigned)N) atomicAdd(&g_dis[c], ew[e]);
}
__global__ void k_rsqrt(int N) {
    int i = blockIdx.x * blockDim.x + threadIdx.x;
    if (i < N) {
        float d = g_dis[i];
        g_dis[i] = d > 0.f ? rsqrtf(fmaxf(d, 1e-12f)) : 0.f;
    }
}
__global__ void k_norm(const int* __restrict__ ei,
                       const float* __restrict__ ew, int E, int N) {
    int e = blockIdx.x * blockDim.x + threadIdx.x;
    if (e >= E) return;
    unsigned r = load_edge(ei, e);
    unsigned c = load_edge(ei, (size_t)E + e);
    g_norm[e] = (r < (unsigned)N && c < (unsigned)N) ? g_dis[r] * ew[e] * g_dis[c] : 0.f;
}

// ---------------- GCN GEMM: XW = A @ W  (W row-major [K,128]) ----------------
// mode 0: A = [x_static | h] (K=144);  mode 1: A = g_x (K=128)
__global__ __launch_bounds__(256) void k_gcn_gemm(const float* __restrict__ xs,
                                                  const float* __restrict__ W,
                                                  int K, int mode, int N) {
    __shared__ float As[8][132];
    __shared__ float Bs[8][128];
    const float* __restrict__ h  = F(g_h4);
    const float* __restrict__ Ap = F(g_x4);
    int bm = blockIdx.x * 128;
    int tid = threadIdx.x;
    int tm = (tid >> 4) << 3;
    int tn = (tid & 15) << 3;
    float acc[8][8] = {};

    for (int k0 = 0; k0 < K; k0 += 8) {
        #pragma unroll
        for (int i = 0; i < 4; i++) {
            int idx = tid + (i << 8);
            int k = idx & 7, m = idx >> 3;
            int gm = bm + m, gk = k0 + k;
            float v = 0.f;
            if (gm < N) {
                if (mode == 0)
                    v = (gk < STAT) ? xs[(size_t)gm * STAT + gk]
                                    : h[(size_t)gm * HID + (gk - STAT)];
                else
                    v = Ap[(size_t)gm * HID + gk];
            }
            As[k][m] = v;
            int n = idx & 127, k2 = idx >> 7;
            Bs[k2][n] = W[(size_t)(k0 + k2) * HID + n];
        }
        __syncthreads();
        #pragma unroll
        for (int k = 0; k < 8; k++) {
            float a[8], b[8];
            #pragma unroll
            for (int i = 0; i < 8; i++) a[i] = As[k][tm + i];
            #pragma unroll
            for (int j = 0; j < 8; j++) b[j] = Bs[k][tn + j];
            #pragma unroll
            for (int i = 0; i < 8; i++)
                #pragma unroll
                for (int j = 0; j < 8; j++) acc[i][j] = fmaf(a[i], b[j], acc[i][j]);
        }
        __syncthreads();
    }
    float* XW = F(g_xw4);
    #pragma unroll
    for (int i = 0; i < 8; i++) {
        int gm = bm + tm + i;
        if (gm >= N) continue;
        #pragma unroll
        for (int j = 0; j < 8; j += 4)
            *(float4*)(XW + (size_t)gm * HID + tn + j) =
                make_float4(acc[i][j], acc[i][j+1], acc[i][j+2], acc[i][j+3]);
    }
}

// agg = dis^2 * xw (self-loop contribution)
__global__ void k_selfinit(int N) {
    int i = blockIdx.x * blockDim.x + threadIdx.x;
    if (i >= N * HID) return;
    int n = i / HID;
    float d = g_dis[n];
    F(g_agg4)[i] = d * d * F(g_xw4)[i];
}

// one warp per edge: agg[col] += norm * xw[row]
__global__ void k_scatter(const int* __restrict__ ei, int E, int N) {
    int gid = blockIdx.x * blockDim.x + threadIdx.x;
    int e = gid >> 5, lane = gid & 31;
    if (e >= E) return;
    unsigned r = load_edge(ei, e);
    unsigned c = load_edge(ei, (size_t)E + e);
    if (r >= (unsigned)N || c >= (unsigned)N) return;
    float nv = g_norm[e];
    float4 v = ((const float4*)(F(g_xw4) + (size_t)r * HID))[lane];
    float* dst = F(g_agg4) + (size_t)c * HID + (lane << 2);
    atomicAdd(dst + 0, nv * v.x);
    atomicAdd(dst + 1, nv * v.y);
    atomicAdd(dst + 2, nv * v.z);
    atomicAdd(dst + 3, nv * v.w);
}

__global__ void k_biasrelu(const float* __restrict__ b, int N) {
    int i = blockIdx.x * blockDim.x + threadIdx.x;
    if (i >= N * HID) return;
    F(g_x4)[i] = fmaxf(F(g_agg4)[i] + b[i % HID], 0.f);
}

// ---------------- output head: warp-per-node dot -----------------------------
__global__ void k_out(const float* __restrict__ Wout, const float* __restrict__ bout,
                      float* __restrict__ out, int N) {
    int gid = blockIdx.x * blockDim.x + threadIdx.x;
    int n = gid >> 5, lane = gid & 31;
    if (n >= N) return;
    float4 xv = ((const float4*)(F(g_x4) + (size_t)n * HID))[lane];
    float4 wv = ((const float4*)Wout)[lane];
    float p = xv.x * wv.x + xv.y * wv.y + xv.z * wv.z + xv.w * wv.w;
    #pragma unroll
    for (int o = 16; o > 0; o >>= 1) p += __shfl_down_sync(0xffffffffu, p, o);
    if (lane == 0) out[n] = p + bout[0];
}

// ---------------- driver ------------------------------------------------------
extern "C" void kernel_launch(void* const* d_in, const int* in_sizes, int n_in,
                              void* d_out, int out_size) {
    const float* xs   = (const float*)d_in[0];
    const float* xd   = (const float*)d_in[1];
    const int*   ei   = (const int*)d_in[2];      // int32 OR int64 (auto-detected)
    const float* ew   = (const float*)d_in[3];
    const float* Wih  = (const float*)d_in[4];
    const float* Whh  = (const float*)d_in[5];
    const float* bih  = (const float*)d_in[6];
    const float* bhh  = (const float*)d_in[7];
    const float* W1   = (const float*)d_in[8];
    const float* b1   = (const float*)d_in[9];
    const float* W2   = (const float*)d_in[10];
    const float* b2   = (const float*)d_in[11];
    const float* W3   = (const float*)d_in[12];
    const float* b3   = (const float*)d_in[13];
    const float* Wout = (const float*)d_in[14];
    const float* bout = (const float*)d_in[15];
    float* out = (float*)d_out;

    int N = in_sizes[0] / STAT;        // 100000
    int E = in_sizes[3];               // 1600000

    int mtiles = (N + 127) / 128;
    int nh4    = N * (HID / 4);
    int nh     = N * HID;

    // combined LSTM weights (transposed) + zero state + edge-dtype detection
    k_build_wcat<<<(KLSTM * G4 + 255) / 256, 256>>>(Wih, Whh, bih, bhh);
    k_det_scan<<<4, 256>>>(ei);
    k_zero_hc<<<(nh + 255) / 256, 256>>>(nh);

    // LSTM recurrence
    for (int t = 0; t < T_STEPS; t++) {
        k_lstm_gemm<<<dim3(mtiles, G4 / 128), 256>>>(xd, t, N);
        k_gates<<<(nh4 + 255) / 256, 256>>>(N);
    }

    // GCN normalization (once)
    k_deg_init<<<(N + 255) / 256, 256>>>(N);
    k_deg_scatter<<<(E + 255) / 256, 256>>>(ei, ew, E, N);
    k_rsqrt<<<(N + 255) / 256, 256>>>(N);
    k_norm<<<(E + 255) / 256, 256>>>(ei, ew, E, N);

    int egrid = (int)(((size_t)E * 32 + 255) / 256);

    // layer 1 (K=144, concat [static|h])
    k_gcn_gemm<<<dim3(mtiles, 1), 256>>>(xs, W1, STAT + HID, 0, N);
    k_selfinit<<<(nh + 255) / 256, 256>>>(N);
    k_scatter<<<egrid, 256>>>(ei, E, N);
    k_biasrelu<<<(nh + 255) / 256, 256>>>(b1, N);

    // layer 2
    k_gcn_gemm<<<dim3(mtiles, 1), 256>>>(xs, W2, HID, 1, N);
    k_selfinit<<<(nh + 255) / 256, 256>>>(N);
    k_scatter<<<egrid, 256>>>(ei, E, N);
    k_biasrelu<<<(nh + 255) / 256, 256>>>(b2, N);

    // layer 3
    k_gcn_gemm<<<dim3(mtiles, 1), 256>>>(xs, W3, HID, 1, N);
    k_selfinit<<<(nh + 255) / 256, 256>>>(N);
    k_scatter<<<egrid, 256>>>(ei, E, N);
    k_biasrelu<<<(nh + 255) / 256, 256>>>(b3, N);

    // head
    k_out<<<(N * 32 + 255) / 256, 256>>>(Wout, bout, out, N);
}

// round 7
// speedup vs baseline: 1.2182x; 1.2182x over previous
#include <cuda_runtime.h>
#include <math.h>

// Problem constants (fixed by the reference)
#define NODES   100000
#define EDGES   1600000
#define HID     128
#define T_STEPS 24
#define DYN     8
#define STAT    16
#define KLSTM   136            // DYN + HID
#define G4      512            // 4*HID gates

// ---------------- scratch (static device globals; no allocation) -------------
__device__ float4 g_h4  [NODES * HID / 4];        // 51.2 MB  LSTM hidden
__device__ float4 g_c4  [NODES * HID / 4];        // 51.2 MB  LSTM cell
__device__ float4 g_z4  [(size_t)NODES * G4 / 4]; // 204.8 MB gate preacts
__device__ float4 g_xw4 [NODES * HID / 4];        // 51.2 MB  X @ W
__device__ float4 g_agg4[NODES * HID / 4];        // 51.2 MB  aggregated
__device__ float4 g_x4  [NODES * HID / 4];        // 51.2 MB  layer activations
__device__ float  g_wcatT[KLSTM * G4];            // [K][512] transposed combined W
__device__ float  g_bcat [G4];
__device__ float  g_dis  [NODES];                 // deg, then deg^-1/2
__device__ float  g_norm [EDGES];
__device__ int    g_any;                          // edge dtype detector: 0 => int64

#define F(p) ((float*)(p))

__device__ __forceinline__ float sg(float x) { return 1.f / (1.f + __expf(-x)); }

// Logical element p of edge_index (shape [2,E] flattened), robust to the
// buffer being int32 OR little-endian int64 (indices < 2^31 => odd words 0).
__device__ __forceinline__ unsigned load_edge(const int* __restrict__ ei, size_t p) {
    return (g_any == 0) ? (unsigned)ei[2 * p]   // int64: low word
                        : (unsigned)ei[p];      // int32
}

// ---------------- setup kernels ---------------------------------------------
__global__ void k_build_wcat(const float* __restrict__ Wih, const float* __restrict__ Whh,
                             const float* __restrict__ bih, const float* __restrict__ bhh) {
    int i = blockIdx.x * blockDim.x + threadIdx.x;
    if (i == 0) g_any = 0;                       // reset detector every call
    if (i < KLSTM * G4) {
        int k = i / G4, g = i % G4;
        g_wcatT[i] = (k < DYN) ? Wih[g * DYN + k] : Whh[g * HID + (k - DYN)];
    }
    if (i < G4) g_bcat[i] = bih[i] + bhh[i];
}

// OR the first 1024 odd 32-bit words: nonzero => int32 layout.
__global__ void k_det_scan(const int* __restrict__ ei) {
    int i = blockIdx.x * blockDim.x + threadIdx.x;   // 1024 threads
    int v = ei[2 * i + 1];
    if (v) atomicOr(&g_any, 1);
}

__global__ void k_zero_hc(int n) {
    int i = blockIdx.x * blockDim.x + threadIdx.x;
    if (i < n) { F(g_h4)[i] = 0.f; F(g_c4)[i] = 0.f; }
}

// ---------------- LSTM step GEMM: Z = [x_t | h] @ WcatT + bcat ---------------
// 128x128 tile, BK=8, 256 threads, 8x8 microtile.
// Double-buffered smem (1 barrier per k-iter), float4 LDS fragments.
__global__ __launch_bounds__(256, 2) void k_lstm_gemm(const float* __restrict__ xd, int t, int N) {
    __shared__ float As[2][8][132];   // pad 132: staging stores conflict-free
    __shared__ float Bs[2][8][128];
    const float* __restrict__ h = F(g_h4);
    const int bm = blockIdx.x * 128;
    const int bn = blockIdx.y * 128;
    const int tid = threadIdx.x;
    const int tm = (tid >> 4) << 3;
    const int tn = (tid & 15) << 3;
    float acc[8][8] = {};
    float ra[4], rb[4];

    const int NIT = KLSTM / 8;        // 17

    // global -> regs for k-block k0
    #define GLOAD(k0)                                                            \
        _Pragma("unroll")                                                        \
        for (int i = 0; i < 4; i++) {                                            \
            int idx = tid + (i << 8);                                            \
            int k = idx & 7, m = idx >> 3;                                       \
            int gm = bm + m, gk = (k0) + k;                                      \
            float v = 0.f;                                                       \
            if (gm < N)                                                          \
                v = (gk < DYN) ? xd[(size_t)gm * (T_STEPS * DYN) + t * DYN + gk] \
                               : h[(size_t)gm * HID + (gk - DYN)];               \
            ra[i] = v;                                                           \
            int n = idx & 127, k2 = idx >> 7;                                    \
            rb[i] = g_wcatT[(size_t)((k0) + k2) * G4 + bn + n];                  \
        }
    #define SSTORE(buf)                                                          \
        _Pragma("unroll")                                                        \
        for (int i = 0; i < 4; i++) {                                            \
            int idx = tid + (i << 8);                                            \
            As[buf][idx & 7][idx >> 3] = ra[i];                                  \
            Bs[buf][idx >> 7][idx & 127] = rb[i];                                \
        }

    GLOAD(0); SSTORE(0); __syncthreads();

    for (int it = 0; it < NIT; it++) {
        const int cur = it & 1;
        if (it + 1 < NIT) { GLOAD((it + 1) * 8); }
        #pragma unroll
        for (int k = 0; k < 8; k++) {
            float4 a0 = *(const float4*)&As[cur][k][tm];
            float4 a1 = *(const float4*)&As[cur][k][tm + 4];
            float4 b0 = *(const float4*)&Bs[cur][k][tn];
            float4 b1 = *(const float4*)&Bs[cur][k][tn + 4];
            float a[8] = {a0.x, a0.y, a0.z, a0.w, a1.x, a1.y, a1.z, a1.w};
            float b[8] = {b0.x, b0.y, b0.z, b0.w, b1.x, b1.y, b1.z, b1.w};
            #pragma unroll
            for (int i = 0; i < 8; i++)
                #pragma unroll
                for (int j = 0; j < 8; j++) acc[i][j] = fmaf(a[i], b[j], acc[i][j]);
        }
        if (it + 1 < NIT) { SSTORE(cur ^ 1); }
        __syncthreads();
    }

    float* Z = F(g_z4);
    #pragma unroll
    for (int i = 0; i < 8; i++) {
        int gm = bm + tm + i;
        if (gm >= N) continue;
        #pragma unroll
        for (int j = 0; j < 8; j += 4) {
            int g = bn + tn + j;
            float4 v = make_float4(acc[i][j]   + g_bcat[g],
                                   acc[i][j+1] + g_bcat[g+1],
                                   acc[i][j+2] + g_bcat[g+2],
                                   acc[i][j+3] + g_bcat[g+3]);
            *(float4*)(Z + (size_t)gm * G4 + g) = v;
        }
    }
}

// ---------------- gate pointwise + state update ------------------------------
__global__ void k_gates(int N) {
    int i = blockIdx.x * blockDim.x + threadIdx.x;   // over N*32 (float4 grains)
    if (i >= N * (HID / 4)) return;
    int n = i >> 5, q = i & 31;
    const float4* z = (const float4*)(F(g_z4) + (size_t)n * G4);
    float4 zi = z[q], zf = z[32 + q], zg = z[64 + q], zo = z[96 + q];
    float4 c = g_c4[i];
    float4 nc, nh;
    nc.x = sg(zf.x) * c.x + sg(zi.x) * tanhf(zg.x);
    nc.y = sg(zf.y) * c.y + sg(zi.y) * tanhf(zg.y);
    nc.z = sg(zf.z) * c.z + sg(zi.z) * tanhf(zg.z);
    nc.w = sg(zf.w) * c.w + sg(zi.w) * tanhf(zg.w);
    nh.x = sg(zo.x) * tanhf(nc.x);
    nh.y = sg(zo.y) * tanhf(nc.y);
    nh.z = sg(zo.z) * tanhf(nc.z);
    nh.w = sg(zo.w) * tanhf(nc.w);
    g_c4[i] = nc;
    g_h4[i] = nh;
}

// ---------------- GCN normalization -----------------------------------------
__global__ void k_deg_init(int N) {
    int i = blockIdx.x * blockDim.x + threadIdx.x;
    if (i < N) g_dis[i] = 1.0f;                       // self-loop weight
}
__global__ void k_deg_scatter(const int* __restrict__ ei,
                              const float* __restrict__ ew, int E, int N) {
    int e = blockIdx.x * blockDim.x + threadIdx.x;
    if (e >= E) return;
    unsigned c = load_edge(ei, (size_t)E + e);
    if (c < (unsigned)N) atomicAdd(&g_dis[c], ew[e]);
}
__global__ void k_rsqrt(int N) {
    int i = blockIdx.x * blockDim.x + threadIdx.x;
    if (i < N) {
        float d = g_dis[i];
        g_dis[i] = d > 0.f ? rsqrtf(fmaxf(d, 1e-12f)) : 0.f;
    }
}
__global__ void k_norm(const int* __restrict__ ei,
                       const float* __restrict__ ew, int E, int N) {
    int e = blockIdx.x * blockDim.x + threadIdx.x;
    if (e >= E) return;
    unsigned r = load_edge(ei, e);
    unsigned c = load_edge(ei, (size_t)E + e);
    g_norm[e] = (r < (unsigned)N && c < (unsigned)N) ? g_dis[r] * ew[e] * g_dis[c] : 0.f;
}

// ---------------- GCN GEMM: XW = A @ W  (W row-major [K,128]) ----------------
// mode 0: A = [x_static | h] (K=144);  mode 1: A = g_x (K=128)
// Same double-buffered structure as the LSTM GEMM.
__global__ __launch_bounds__(256, 2) void k_gcn_gemm(const float* __restrict__ xs,
                                                     const float* __restrict__ W,
                                                     int K, int mode, int N) {
    __shared__ float As[2][8][132];
    __shared__ float Bs[2][8][128];
    const float* __restrict__ h  = F(g_h4);
    const float* __restrict__ Ap = F(g_x4);
    const int bm = blockIdx.x * 128;
    const int tid = threadIdx.x;
    const int tm = (tid >> 4) << 3;
    const int tn = (tid & 15) << 3;
    float acc[8][8] = {};
    float ra[4], rb[4];
    const int NIT = K / 8;

    #define GGLOAD(k0)                                                           \
        _Pragma("unroll")                                                        \
        for (int i = 0; i < 4; i++) {                                            \
            int idx = tid + (i << 8);                                            \
            int k = idx & 7, m = idx >> 3;                                       \
            int gm = bm + m, gk = (k0) + k;                                      \
            float v = 0.f;                                                       \
            if (gm < N) {                                                        \
                if (mode == 0)                                                   \
                    v = (gk < STAT) ? xs[(size_t)gm * STAT + gk]                 \
                                    : h[(size_t)gm * HID + (gk - STAT)];         \
                else                                                             \
                    v = Ap[(size_t)gm * HID + gk];                               \
            }                                                                    \
            ra[i] = v;                                                           \
            int n = idx & 127, k2 = idx >> 7;                                    \
            rb[i] = W[(size_t)((k0) + k2) * HID + n];                            \
        }

    GGLOAD(0); SSTORE(0); __syncthreads();

    for (int it = 0; it < NIT; it++) {
        const int cur = it & 1;
        if (it + 1 < NIT) { GGLOAD((it + 1) * 8); }
        #pragma unroll
        for (int k = 0; k < 8; k++) {
            float4 a0 = *(const float4*)&As[cur][k][tm];
            float4 a1 = *(const float4*)&As[cur][k][tm + 4];
            float4 b0 = *(const float4*)&Bs[cur][k][tn];
            float4 b1 = *(const float4*)&Bs[cur][k][tn + 4];
            float a[8] = {a0.x, a0.y, a0.z, a0.w, a1.x, a1.y, a1.z, a1.w};
            float b[8] = {b0.x, b0.y, b0.z, b0.w, b1.x, b1.y, b1.z, b1.w};
            #pragma unroll
            for (int i = 0; i < 8; i++)
                #pragma unroll
                for (int j = 0; j < 8; j++) acc[i][j] = fmaf(a[i], b[j], acc[i][j]);
        }
        if (it + 1 < NIT) { SSTORE(cur ^ 1); }
        __syncthreads();
    }

    float* XW = F(g_xw4);
    #pragma unroll
    for (int i = 0; i < 8; i++) {
        int gm = bm + tm + i;
        if (gm >= N) continue;
        #pragma unroll
        for (int j = 0; j < 8; j += 4)
            *(float4*)(XW + (size_t)gm * HID + tn + j) =
                make_float4(acc[i][j], acc[i][j+1], acc[i][j+2], acc[i][j+3]);
    }
}

// agg = dis^2 * xw (self-loop contribution)
__global__ void k_selfinit(int N) {
    int i = blockIdx.x * blockDim.x + threadIdx.x;
    if (i >= N * HID) return;
    int n = i / HID;
    float d = g_dis[n];
    F(g_agg4)[i] = d * d * F(g_xw4)[i];
}

// one warp per edge: agg[col] += norm * xw[row]
__global__ void k_scatter(const int* __restrict__ ei, int E, int N) {
    int gid = blockIdx.x * blockDim.x + threadIdx.x;
    int e = gid >> 5, lane = gid & 31;
    if (e >= E) return;
    unsigned r = load_edge(ei, e);
    unsigned c = load_edge(ei, (size_t)E + e);
    if (r >= (unsigned)N || c >= (unsigned)N) return;
    float nv = g_norm[e];
    float4 v = ((const float4*)(F(g_xw4) + (size_t)r * HID))[lane];
    float* dst = F(g_agg4) + (size_t)c * HID + (lane << 2);
    atomicAdd(dst + 0, nv * v.x);
    atomicAdd(dst + 1, nv * v.y);
    atomicAdd(dst + 2, nv * v.z);
    atomicAdd(dst + 3, nv * v.w);
}

__global__ void k_biasrelu(const float* __restrict__ b, int N) {
    int i = blockIdx.x * blockDim.x + threadIdx.x;
    if (i >= N * HID) return;
    F(g_x4)[i] = fmaxf(F(g_agg4)[i] + b[i % HID], 0.f);
}

// ---------------- output head: warp-per-node dot -----------------------------
__global__ void k_out(const float* __restrict__ Wout, const float* __restrict__ bout,
                      float* __restrict__ out, int N) {
    int gid = blockIdx.x * blockDim.x + threadIdx.x;
    int n = gid >> 5, lane = gid & 31;
    if (n >= N) return;
    float4 xv = ((const float4*)(F(g_x4) + (size_t)n * HID))[lane];
    float4 wv = ((const float4*)Wout)[lane];
    float p = xv.x * wv.x + xv.y * wv.y + xv.z * wv.z + xv.w * wv.w;
    #pragma unroll
    for (int o = 16; o > 0; o >>= 1) p += __shfl_down_sync(0xffffffffu, p, o);
    if (lane == 0) out[n] = p + bout[0];
}

// ---------------- driver ------------------------------------------------------
extern "C" void kernel_launch(void* const* d_in, const int* in_sizes, int n_in,
                              void* d_out, int out_size) {
    const float* xs   = (const float*)d_in[0];
    const float* xd   = (const float*)d_in[1];
    const int*   ei   = (const int*)d_in[2];      // int32 OR int64 (auto-detected)
    const float* ew   = (const float*)d_in[3];
    const float* Wih  = (const float*)d_in[4];
    const float* Whh  = (const float*)d_in[5];
    const float* bih  = (const float*)d_in[6];
    const float* bhh  = (const float*)d_in[7];
    const float* W1   = (const float*)d_in[8];
    const float* b1   = (const float*)d_in[9];
    const float* W2   = (const float*)d_in[10];
    const float* b2   = (const float*)d_in[11];
    const float* W3   = (const float*)d_in[12];
    const float* b3   = (const float*)d_in[13];
    const float* Wout = (const float*)d_in[14];
    const float* bout = (const float*)d_in[15];
    float* out = (float*)d_out;

    int N = in_sizes[0] / STAT;        // 100000
    int E = in_sizes[3];               // 1600000

    int mtiles = (N + 127) / 128;
    int nh4    = N * (HID / 4);
    int nh     = N * HID;

    // combined LSTM weights (transposed) + zero state + edge-dtype detection
    k_build_wcat<<<(KLSTM * G4 + 255) / 256, 256>>>(Wih, Whh, bih, bhh);
    k_det_scan<<<4, 256>>>(ei);
    k_zero_hc<<<(nh + 255) / 256, 256>>>(nh);

    // LSTM recurrence
    for (int t = 0; t < T_STEPS; t++) {
        k_lstm_gemm<<<dim3(mtiles, G4 / 128), 256>>>(xd, t, N);
        k_gates<<<(nh4 + 255) / 256, 256>>>(N);
    }

    // GCN normalization (once)
    k_deg_init<<<(N + 255) / 256, 256>>>(N);
    k_deg_scatter<<<(E + 255) / 256, 256>>>(ei, ew, E, N);
    k_rsqrt<<<(N + 255) / 256, 256>>>(N);
    k_norm<<<(E + 255) / 256, 256>>>(ei, ew, E, N);

    int egrid = (int)(((size_t)E * 32 + 255) / 256);

    // layer 1 (K=144, concat [static|h])
    k_gcn_gemm<<<dim3(mtiles, 1), 256>>>(xs, W1, STAT + HID, 0, N);
    k_selfinit<<<(nh + 255) / 256, 256>>>(N);
    k_scatter<<<egrid, 256>>>(ei, E, N);
    k_biasrelu<<<(nh + 255) / 256, 256>>>(b1, N);

    // layer 2
    k_gcn_gemm<<<dim3(mtiles, 1), 256>>>(xs, W2, HID, 1, N);
    k_selfinit<<<(nh + 255) / 256, 256>>>(N);
    k_scatter<<<egrid, 256>>>(ei, E, N);
    k_biasrelu<<<(nh + 255) / 256, 256>>>(b2, N);

    // layer 3
    k_gcn_gemm<<<dim3(mtiles, 1), 256>>>(xs, W3, HID, 1, N);
    k_selfinit<<<(nh + 255) / 256, 256>>>(N);
    k_scatter<<<egrid, 256>>>(ei, E, N);
    k_biasrelu<<<(nh + 255) / 256, 256>>>(b3, N);

    // head
    k_out<<<(N * 32 + 255) / 256, 256>>>(Wout, bout, out, N);
}